// round 11
// baseline (speedup 1.0000x reference)
#include <cuda_runtime.h>
#include <cuda_fp16.h>
#include <cstdint>

#define B_ 256
#define T_ 512
#define R_ 2048
#define O_ 10

#define KCH_B 4096                 // bytes of one k32 A-or-B sub-chunk (fragment order)
#define STAGE_B (2*KCH_B)          // A + B = 8 KB
#define NGROUP 8
#define SMEM_BYTES (3*NGROUP*STAGE_B)   // 3 stages x 8 groups = 192 KB

// ---------------- device scratch ----------------
__device__ __align__(128) float    g_H[2][B_ * R_];              // fp32 state
__device__ __align__(128) uint32_t g_Hh[2][4 * 32 * 2048];       // fp16 A operand, fragment order
__device__ __align__(128) uint32_t g_Xh[T_ * 4 * 2048];          // fp16 x chunks, fragment order
__device__ __align__(128) uint32_t g_Wh[32 * 33 * 2048];         // fp16 B operand, fragment order

__device__ __forceinline__ void cp16(void* dst, const void* src) {
    uint32_t d = (uint32_t)__cvta_generic_to_shared(dst);
    asm volatile("cp.async.cg.shared.global [%0], [%1], 16;\n" :: "r"(d), "l"(src));
}

#define MMA(cc, av, bb0, bb1) \
    asm volatile("mma.sync.aligned.m16n8k16.row.col.f32.f16.f16.f32 " \
        "{%0,%1,%2,%3},{%4,%5,%6,%7},{%8,%9},{%0,%1,%2,%3};\n" \
        : "+f"((cc)[0]), "+f"((cc)[1]), "+f"((cc)[2]), "+f"((cc)[3]) \
        : "r"((av).x), "r"((av).y), "r"((av).z), "r"((av).w), "r"(bb0), "r"(bb1))

// ---------------- prep: permute + fp16-round operands once ----------------
// A chunk (64m x 64k): u32 idx = (k16*4 + mh*2 + mi)*128 + lane*4 + (rhi + 2*khalf)
// B chunk (64k x 64n): u32 idx = ((k16*2 + nh)*32 + lane)*8 + (ni>>1)*4 + (ni&1)*2 + khalf
__global__ void prep_W(const float* __restrict__ Wres, const float* __restrict__ Win) {
    uint32_t idx = blockIdx.x * 256u + threadIdx.x;      // 1056*2048 k-pairs
    uint32_t k2 = idx >> 11, n = idx & 2047u;
    uint32_t k = k2 * 2u;
    float v0, v1;
    if (k < 2048u) { v0 = Wres[(size_t)k * R_ + n]; v1 = Wres[(size_t)(k + 1) * R_ + n]; }
    else           { v0 = Win[(size_t)(k - 2048u) * R_ + n]; v1 = Win[(size_t)(k - 2047u) * R_ + n]; }
    uint32_t kc = k >> 6, kl = k & 63u;
    uint32_t k16 = kl >> 4, kin = kl & 15u, khalf = kin >> 3, tg = (kin & 7u) >> 1;
    uint32_t g = n & 7u, ni = (n >> 3) & 3u, nh = (n >> 5) & 1u, bn = n >> 6;
    uint32_t lane = g * 4u + tg;
    __half2 h = __floats2half2_rn(v0, v1);
    g_Wh[(bn * 33u + kc) * 2048u + ((k16 * 2u + nh) * 32u + lane) * 8u
         + (ni >> 1) * 4u + (ni & 1u) * 2u + khalf] = *(uint32_t*)&h;
}

__global__ void prep_X(const float* __restrict__ x) {
    uint32_t idx = blockIdx.x * 256u + threadIdx.x;      // 256*512*32 i-pairs
    uint32_t b = idx >> 14, t = (idx >> 5) & 511u, i = (idx & 31u) * 2u;
    float2 v = *(const float2*)(x + ((size_t)b * T_ + t) * 64u + i);
    uint32_t k16 = i >> 4, kin = i & 15u, khalf = kin >> 3, tg = (kin & 7u) >> 1;
    uint32_t g = b & 7u, rhi = (b >> 3) & 1u, mi = (b >> 4) & 1u, mh = (b >> 5) & 1u, bm = b >> 6;
    uint32_t lane = g * 4u + tg;
    __half2 h = __floats2half2_rn(v.x, v.y);
    g_Xh[(t * 4u + bm) * 2048u + ((k16 * 4u + mh * 2u + mi) * 32u + lane) * 4u
         + rhi + 2u * khalf] = *(uint32_t*)&h;
}

__global__ void esn_zero() {
    uint32_t i = blockIdx.x * 256u + threadIdx.x;        // 131072
    ((float4*)g_H[0])[i] = make_float4(0.f, 0.f, 0.f, 0.f);
    if (i < 65536u) ((uint4*)g_Hh[0])[i] = make_uint4(0u, 0u, 0u, 0u);
}

// ---------------- step: H_new = 0.5H + 0.5 tanh([H|x_t] @ Wcat) ----------------
// 256 threads = 8 single-warp split-K groups. Warp tile = full 64x64 CTA tile;
// group g streams k32 tiles kt=8j+g through a private 3-stage cp.async pipeline.
// No block barriers in the mainloop (producer == consumer warp).
__global__ __launch_bounds__(256, 1) void esn_step(int t)
{
    extern __shared__ char smem[];
    const int tid = threadIdx.x;
    const int gid = tid >> 5, lane = tid & 31;           // 8 groups = 8 warps
    const int bn = blockIdx.x, bm = blockIdx.y;
    const int cur = t & 1, nxt = cur ^ 1;
    char* gsm = smem + gid * 3 * STAGE_B;
    const int NCH = (gid < 2) ? 9 : 8;

    __align__(16) float c[4][8][4];
#pragma unroll
    for (int q = 0; q < 4; q++)
#pragma unroll
        for (int no = 0; no < 8; no++)
#pragma unroll
            for (int i = 0; i < 4; i++) c[q][no][i] = 0.f;

    auto issue = [&](int j) {
        const int kt = 8 * j + gid;                      // k32 tile 0..65
        char* dst = gsm + (j % 3) * STAGE_B;
        const uint32_t* a = (kt < 64)
            ? (g_Hh[cur] + (size_t)(bm * 32 + (kt >> 1)) * 2048 + (kt & 1) * 1024)
            : (g_Xh + (size_t)(t * 4 + bm) * 2048 + (kt & 1) * 1024);
        const uint32_t* b = g_Wh + (size_t)(bn * 33 + (kt >> 1)) * 2048 + (kt & 1) * 1024;
#pragma unroll
        for (int it = 0; it < 8; it++) { int e = (it * 32 + lane) * 4; cp16(dst + e * 4, a + e); }
#pragma unroll
        for (int it = 0; it < 8; it++) { int e = (it * 32 + lane) * 4; cp16(dst + KCH_B + e * 4, b + e); }
        asm volatile("cp.async.commit_group;\n" ::);
    };

    issue(0); issue(1);

    for (int j = 0; j < NCH; j++) {
        if (j < NCH - 1) asm volatile("cp.async.wait_group 1;\n" ::);
        else             asm volatile("cp.async.wait_group 0;\n" ::);
        __syncwarp();                                    // cross-lane visibility of cp.async
        if (j + 2 < NCH) issue(j + 2);

        const uint4* sA = (const uint4*)(gsm + (j % 3) * STAGE_B);
        const uint4* sB = (const uint4*)(gsm + (j % 3) * STAGE_B + KCH_B);
#pragma unroll
        for (int kl = 0; kl < 2; kl++) {                 // two k16 per k32 tile
            uint4 fa[4], fb[4];
#pragma unroll
            for (int q = 0; q < 4; q++) fa[q] = sA[(kl * 4 + q) * 32 + lane];
#pragma unroll
            for (int u = 0; u < 4; u++)
                fb[u] = sB[((kl * 2 + (u >> 1)) * 32 + lane) * 2 + (u & 1)];
#pragma unroll
            for (int q = 0; q < 4; q++)
#pragma unroll
                for (int u = 0; u < 4; u++) {
                    const int no = (u >> 1) * 4 + (u & 1) * 2;
                    MMA(c[q][no],     fa[q], fb[u].x, fb[u].y);
                    MMA(c[q][no + 1], fa[q], fb[u].z, fb[u].w);
                }
        }
    }

    // ---------------- combine 8 split-K partials + epilogue ----------------
    // part[f 0..31][gid 0..7][lane] float4 = 128 KB (reuses pipeline smem).
    __syncthreads();
    float4* part = (float4*)smem;
#pragma unroll
    for (int f = 0; f < 32; f++)
        part[(f * 8 + gid) * 32 + lane] = *(const float4*)c[f >> 3][f & 7];
    __syncthreads();

    // Warp gid reduces fragments f = gid*4 .. gid*4+3 and runs their epilogue.
#pragma unroll
    for (int fi = 0; fi < 4; fi++) {
        const int f = gid * 4 + fi;
        const float4* p = part + (f * 8) * 32 + lane;
        float4 s0 = p[0 * 32], s1 = p[1 * 32], s2 = p[2 * 32], s3 = p[3 * 32];
        float4 s4 = p[4 * 32], s5 = p[5 * 32], s6 = p[6 * 32], s7 = p[7 * 32];
        float v[4];
        v[0] = ((s0.x + s1.x) + (s2.x + s3.x)) + ((s4.x + s5.x) + (s6.x + s7.x));
        v[1] = ((s0.y + s1.y) + (s2.y + s3.y)) + ((s4.y + s5.y) + (s6.y + s7.y));
        v[2] = ((s0.z + s1.z) + (s2.z + s3.z)) + ((s4.z + s5.z) + (s6.z + s7.z));
        v[3] = ((s0.w + s1.w) + (s2.w + s3.w)) + ((s4.w + s5.w) + (s6.w + s7.w));

        const int q = f >> 3, no = f & 7;
        const int nh = no >> 2, ni = no & 3;
        const int gg = lane >> 2, tgg = lane & 3;
        const int col = bn * 64 + nh * 32 + ni * 8 + tgg * 2;
#pragma unroll
        for (int rhi = 0; rhi < 2; rhi++) {
            const int row = bm * 64 + q * 16 + rhi * 8 + gg;
            const float2 ho = *(const float2*)(g_H[cur] + (size_t)row * R_ + col);
            float h0 = 0.5f * ho.x + 0.5f * tanhf(v[2 * rhi]);
            float h1 = 0.5f * ho.y + 0.5f * tanhf(v[2 * rhi + 1]);
            *(float2*)(g_H[nxt] + (size_t)row * R_ + col) = make_float2(h0, h1);
            __half2 hh = __floats2half2_rn(h0, h1);
            const uint32_t off = (uint32_t)(bm * 32 + bn) * 2048u
                + (uint32_t)((nh * 2 + (ni >> 1)) * 4 + (q >> 1) * 2 + (q & 1)) * 128u
                + (uint32_t)lane * 4u + (uint32_t)(rhi + 2 * (ni & 1));
            g_Hh[nxt][off] = *(uint32_t*)&hh;
        }
    }
}

// ---------------- readout ----------------
__global__ void esn_readout(const float* __restrict__ W_out,
                            const float* __restrict__ b_out,
                            float* __restrict__ out)
{
    int b = blockIdx.x, tid = threadIdx.x;
    const float* h = g_H[0] + (size_t)b * R_;
    float acc[O_];
#pragma unroll
    for (int o = 0; o < O_; o++) acc[o] = 0.f;
    for (int r = tid; r < R_; r += 256) {
        float hv = h[r];
#pragma unroll
        for (int o = 0; o < O_; o++) acc[o] += hv * W_out[r * O_ + o];
    }
#pragma unroll
    for (int o = 0; o < O_; o++)
#pragma unroll
        for (int off = 16; off > 0; off >>= 1)
            acc[o] += __shfl_down_sync(0xffffffffu, acc[o], off);
    __shared__ float s[8][O_];
    if ((tid & 31) == 0)
#pragma unroll
        for (int o = 0; o < O_; o++) s[tid >> 5][o] = acc[o];
    __syncthreads();
    if (tid < O_) {
        float v = b_out[tid];
#pragma unroll
        for (int w = 0; w < 8; w++) v += s[w][tid];
        out[b * O_ + tid] = v;
    }
}

extern "C" void kernel_launch(void* const* d_in, const int* in_sizes, int n_in,
                              void* d_out, int out_size)
{
    const float* x     = (const float*)d_in[0];
    const float* W_in  = (const float*)d_in[1];
    const float* W_res = (const float*)d_in[2];
    const float* W_out = (const float*)d_in[3];
    const float* b_out = (const float*)d_in[4];
    float* out = (float*)d_out;

    cudaFuncSetAttribute(esn_step, cudaFuncAttributeMaxDynamicSharedMemorySize, SMEM_BYTES);

    prep_W<<<(1056 * 2048) / 256, 256>>>(W_res, W_in);
    prep_X<<<(B_ * T_ * 32) / 256, 256>>>(x);
    esn_zero<<<512, 256>>>();

    dim3 grid(32, 4);   // bn x bm = 128 CTAs, 1 per SM
    for (int t = 0; t < T_; t++)
        esn_step<<<grid, 256, SMEM_BYTES>>>(t);

    esn_readout<<<B_, 256>>>(W_out, b_out, out);
}

// round 12
// speedup vs baseline: 1.0468x; 1.0468x over previous
#include <cuda_runtime.h>
#include <cuda_fp16.h>
#include <cstdint>

#define B_ 256
#define T_ 512
#define R_ 2048
#define O_ 10

#define KCH_B 4096                 // bytes of one k32 A-or-B sub-chunk (fragment order)
#define STAGE_B (2*KCH_B)          // A + B = 8 KB
#define NGROUP 6
#define SMEM_BYTES (3*NGROUP*STAGE_B)   // 3 stages x 6 groups = 144 KB

// ---------------- device scratch ----------------
__device__ __align__(128) float    g_H[2][B_ * R_];              // fp32 state
__device__ __align__(128) uint32_t g_Hh[2][4 * 32 * 2048];       // fp16 A operand, fragment order
__device__ __align__(128) uint32_t g_Xh[T_ * 4 * 2048];          // fp16 x chunks, fragment order
__device__ __align__(128) uint32_t g_Wh[32 * 33 * 2048];         // fp16 B operand, fragment order

__device__ __forceinline__ void cp16(void* dst, const void* src) {
    uint32_t d = (uint32_t)__cvta_generic_to_shared(dst);
    asm volatile("cp.async.cg.shared.global [%0], [%1], 16;\n" :: "r"(d), "l"(src));
}
__device__ __forceinline__ float tanh_fast(float x) {
    float r; asm("tanh.approx.f32 %0, %1;" : "=f"(r) : "f"(x)); return r;
}

#define MMA(cc, av, bb0, bb1) \
    asm volatile("mma.sync.aligned.m16n8k16.row.col.f32.f16.f16.f32 " \
        "{%0,%1,%2,%3},{%4,%5,%6,%7},{%8,%9},{%0,%1,%2,%3};\n" \
        : "+f"((cc)[0]), "+f"((cc)[1]), "+f"((cc)[2]), "+f"((cc)[3]) \
        : "r"((av).x), "r"((av).y), "r"((av).z), "r"((av).w), "r"(bb0), "r"(bb1))

// ---------------- prep: permute + fp16-round operands once ----------------
__global__ void prep_W(const float* __restrict__ Wres, const float* __restrict__ Win) {
    uint32_t idx = blockIdx.x * 256u + threadIdx.x;      // 1056*2048 k-pairs
    uint32_t k2 = idx >> 11, n = idx & 2047u;
    uint32_t k = k2 * 2u;
    float v0, v1;
    if (k < 2048u) { v0 = Wres[(size_t)k * R_ + n]; v1 = Wres[(size_t)(k + 1) * R_ + n]; }
    else           { v0 = Win[(size_t)(k - 2048u) * R_ + n]; v1 = Win[(size_t)(k - 2047u) * R_ + n]; }
    uint32_t kc = k >> 6, kl = k & 63u;
    uint32_t k16 = kl >> 4, kin = kl & 15u, khalf = kin >> 3, tg = (kin & 7u) >> 1;
    uint32_t g = n & 7u, ni = (n >> 3) & 3u, nh = (n >> 5) & 1u, bn = n >> 6;
    uint32_t lane = g * 4u + tg;
    __half2 h = __floats2half2_rn(v0, v1);
    g_Wh[(bn * 33u + kc) * 2048u + ((k16 * 2u + nh) * 32u + lane) * 8u
         + (ni >> 1) * 4u + (ni & 1u) * 2u + khalf] = *(uint32_t*)&h;
}

__global__ void prep_X(const float* __restrict__ x) {
    uint32_t idx = blockIdx.x * 256u + threadIdx.x;      // 256*512*32 i-pairs
    uint32_t b = idx >> 14, t = (idx >> 5) & 511u, i = (idx & 31u) * 2u;
    float2 v = *(const float2*)(x + ((size_t)b * T_ + t) * 64u + i);
    uint32_t k16 = i >> 4, kin = i & 15u, khalf = kin >> 3, tg = (kin & 7u) >> 1;
    uint32_t g = b & 7u, rhi = (b >> 3) & 1u, mi = (b >> 4) & 1u, mh = (b >> 5) & 1u, bm = b >> 6;
    uint32_t lane = g * 4u + tg;
    __half2 h = __floats2half2_rn(v.x, v.y);
    g_Xh[(t * 4u + bm) * 2048u + ((k16 * 4u + mh * 2u + mi) * 32u + lane) * 4u
         + rhi + 2u * khalf] = *(uint32_t*)&h;
}

__global__ void esn_zero() {
    uint32_t i = blockIdx.x * 256u + threadIdx.x;        // 131072
    ((float4*)g_H[0])[i] = make_float4(0.f, 0.f, 0.f, 0.f);
    if (i < 65536u) ((uint4*)g_Hh[0])[i] = make_uint4(0u, 0u, 0u, 0u);
}

// ---------------- step: H_new = 0.5H + 0.5 tanh([H|x_t] @ Wcat) ----------------
// 384 threads = 6 warp-groups of 2 warps. Group g: split-K over k32 tiles
// kt = 6j+g, j=0..10 (uniform 11 chunks; kt 64,65 = x tiles). Warp tile 64x32.
// Private 3-stage cp.async pipeline + 64-thread named barrier per group.
// Intra-stage fragment double-buffering across the two k16 sub-steps.
__global__ __launch_bounds__(384, 1) void esn_step(int t)
{
    extern __shared__ char smem[];
    const int tid = threadIdx.x;
    const int gid = tid >> 6, gtid = tid & 63;           // 6 groups of 64 threads
    const int warp = gtid >> 5, lane = gtid & 31;        // warp = n-half (0/1)
    const int bn = blockIdx.x, bm = blockIdx.y;
    const int cur = t & 1, nxt = cur ^ 1;
    char* gsm = smem + gid * 3 * STAGE_B;
    const int NCH = 11;

    __align__(16) float c[4][4][4];
#pragma unroll
    for (int mi = 0; mi < 4; mi++)
#pragma unroll
        for (int nq = 0; nq < 4; nq++)
#pragma unroll
            for (int i = 0; i < 4; i++) c[mi][nq][i] = 0.f;

    auto issue = [&](int j) {
        const int kt = 6 * j + gid;                      // k32 tile 0..65
        char* dst = gsm + (j % 3) * STAGE_B;
        const uint32_t* a = (kt < 64)
            ? (g_Hh[cur] + (size_t)(bm * 32 + (kt >> 1)) * 2048 + (kt & 1) * 1024)
            : (g_Xh + (size_t)(t * 4 + bm) * 2048 + (kt & 1) * 1024);
        const uint32_t* b = g_Wh + (size_t)(bn * 33 + (kt >> 1)) * 2048 + (kt & 1) * 1024;
#pragma unroll
        for (int it = 0; it < 4; it++) { int e = (it * 64 + gtid) * 4; cp16(dst + e * 4, a + e); }
#pragma unroll
        for (int it = 0; it < 4; it++) { int e = (it * 64 + gtid) * 4; cp16(dst + KCH_B + e * 4, b + e); }
        asm volatile("cp.async.commit_group;\n" ::);
    };

    issue(0); issue(1);

    for (int j = 0; j < NCH; j++) {
        if (j < NCH - 1) asm volatile("cp.async.wait_group 1;\n" ::);
        else             asm volatile("cp.async.wait_group 0;\n" ::);
        asm volatile("bar.sync %0, 64;" :: "r"(gid + 1) : "memory");
        if (j + 2 < NCH) issue(j + 2);

        const uint4* sA = (const uint4*)(gsm + (j % 3) * STAGE_B);
        const uint4* sB = (const uint4*)(gsm + (j % 3) * STAGE_B + KCH_B);

        uint4 fa[2][4], fb[2][2];
#pragma unroll
        for (int q = 0; q < 4; q++) fa[0][q] = sA[q * 32 + lane];
        fb[0][0] = sB[(warp * 32 + lane) * 2];
        fb[0][1] = sB[(warp * 32 + lane) * 2 + 1];
#pragma unroll
        for (int kl = 0; kl < 2; kl++) {                 // two k16 per k32 tile
            if (kl == 0) {                               // prefetch kl=1 fragments
#pragma unroll
                for (int q = 0; q < 4; q++) fa[1][q] = sA[(4 + q) * 32 + lane];
                fb[1][0] = sB[((2 + warp) * 32 + lane) * 2];
                fb[1][1] = sB[((2 + warp) * 32 + lane) * 2 + 1];
            }
            MMA(c[0][0], fa[kl][0], fb[kl][0].x, fb[kl][0].y);
            MMA(c[0][1], fa[kl][0], fb[kl][0].z, fb[kl][0].w);
            MMA(c[0][2], fa[kl][0], fb[kl][1].x, fb[kl][1].y);
            MMA(c[0][3], fa[kl][0], fb[kl][1].z, fb[kl][1].w);
            MMA(c[1][0], fa[kl][1], fb[kl][0].x, fb[kl][0].y);
            MMA(c[1][1], fa[kl][1], fb[kl][0].z, fb[kl][0].w);
            MMA(c[1][2], fa[kl][1], fb[kl][1].x, fb[kl][1].y);
            MMA(c[1][3], fa[kl][1], fb[kl][1].z, fb[kl][1].w);
            MMA(c[2][0], fa[kl][2], fb[kl][0].x, fb[kl][0].y);
            MMA(c[2][1], fa[kl][2], fb[kl][0].z, fb[kl][0].w);
            MMA(c[2][2], fa[kl][2], fb[kl][1].x, fb[kl][1].y);
            MMA(c[2][3], fa[kl][2], fb[kl][1].z, fb[kl][1].w);
            MMA(c[3][0], fa[kl][3], fb[kl][0].x, fb[kl][0].y);
            MMA(c[3][1], fa[kl][3], fb[kl][0].z, fb[kl][0].w);
            MMA(c[3][2], fa[kl][3], fb[kl][1].x, fb[kl][1].y);
            MMA(c[3][3], fa[kl][3], fb[kl][1].z, fb[kl][1].w);
        }
    }

    // ---------------- combine 6 split-K partials + epilogue ----------------
    // part[f 0..15][w 0..1][gid 0..5][lane] float4 = 96 KB (reuses pipeline smem).
    __syncthreads();
    float4* part = (float4*)smem;
#pragma unroll
    for (int mi = 0; mi < 4; mi++)
#pragma unroll
        for (int nq = 0; nq < 4; nq++) {
            const int f = mi * 4 + nq;
            part[((f * 2 + warp) * 6 + gid) * 32 + lane] = *(const float4*)c[mi][nq];
        }
    __syncthreads();

    // 1024 slots (fp 0..15, w 0..1, ln 0..31) over 384 threads.
    for (int s = tid; s < 1024; s += 384) {
        const int fp = s >> 6, w = (s >> 5) & 1, ln = s & 31;
        const int gg = ln >> 2, tgg = ln & 3;
        const float4* p = part + ((fp * 2 + w) * 6) * 32 + ln;
        float4 s0 = p[0 * 32], s1 = p[1 * 32], s2 = p[2 * 32];
        float4 s3 = p[3 * 32], s4 = p[4 * 32], s5 = p[5 * 32];
        float v[4];
        v[0] = ((s0.x + s1.x) + (s2.x + s3.x)) + (s4.x + s5.x);
        v[1] = ((s0.y + s1.y) + (s2.y + s3.y)) + (s4.y + s5.y);
        v[2] = ((s0.z + s1.z) + (s2.z + s3.z)) + (s4.z + s5.z);
        v[3] = ((s0.w + s1.w) + (s2.w + s3.w)) + (s4.w + s5.w);

        const int mi = fp >> 2, nq = fp & 3;
        const int col = bn * 64 + w * 32 + nq * 8 + tgg * 2;
#pragma unroll
        for (int rhi = 0; rhi < 2; rhi++) {
            const int row = bm * 64 + mi * 16 + rhi * 8 + gg;
            const float2 ho = *(const float2*)(g_H[cur] + (size_t)row * R_ + col);
            float h0 = 0.5f * ho.x + 0.5f * tanh_fast(v[2 * rhi]);
            float h1 = 0.5f * ho.y + 0.5f * tanh_fast(v[2 * rhi + 1]);
            *(float2*)(g_H[nxt] + (size_t)row * R_ + col) = make_float2(h0, h1);
            __half2 hh = __floats2half2_rn(h0, h1);
            const uint32_t off = (uint32_t)(bm * 32 + bn) * 2048u
                + (uint32_t)((w * 2 + (nq >> 1)) * 4 + (mi >> 1) * 2 + (mi & 1)) * 128u
                + (uint32_t)ln * 4u + (uint32_t)(rhi + 2 * (nq & 1));
            g_Hh[nxt][off] = *(uint32_t*)&hh;
        }
    }
}

// ---------------- readout ----------------
__global__ void esn_readout(const float* __restrict__ W_out,
                            const float* __restrict__ b_out,
                            float* __restrict__ out)
{
    int b = blockIdx.x, tid = threadIdx.x;
    const float* h = g_H[0] + (size_t)b * R_;
    float acc[O_];
#pragma unroll
    for (int o = 0; o < O_; o++) acc[o] = 0.f;
    for (int r = tid; r < R_; r += 256) {
        float hv = h[r];
#pragma unroll
        for (int o = 0; o < O_; o++) acc[o] += hv * W_out[r * O_ + o];
    }
#pragma unroll
    for (int o = 0; o < O_; o++)
#pragma unroll
        for (int off = 16; off > 0; off >>= 1)
            acc[o] += __shfl_down_sync(0xffffffffu, acc[o], off);
    __shared__ float s[8][O_];
    if ((tid & 31) == 0)
#pragma unroll
        for (int o = 0; o < O_; o++) s[tid >> 5][o] = acc[o];
    __syncthreads();
    if (tid < O_) {
        float v = b_out[tid];
#pragma unroll
        for (int w = 0; w < 8; w++) v += s[w][tid];
        out[b * O_ + tid] = v;
    }
}

extern "C" void kernel_launch(void* const* d_in, const int* in_sizes, int n_in,
                              void* d_out, int out_size)
{
    const float* x     = (const float*)d_in[0];
    const float* W_in  = (const float*)d_in[1];
    const float* W_res = (const float*)d_in[2];
    const float* W_out = (const float*)d_in[3];
    const float* b_out = (const float*)d_in[4];
    float* out = (float*)d_out;

    cudaFuncSetAttribute(esn_step, cudaFuncAttributeMaxDynamicSharedMemorySize, SMEM_BYTES);

    prep_W<<<(1056 * 2048) / 256, 256>>>(W_res, W_in);
    prep_X<<<(B_ * T_ * 32) / 256, 256>>>(x);
    esn_zero<<<512, 256>>>();

    dim3 grid(32, 4);   // bn x bm = 128 CTAs, 1 per SM
    for (int t = 0; t < T_; t++)
        esn_step<<<grid, 384, SMEM_BYTES>>>(t);

    esn_readout<<<B_, 256>>>(W_out, b_out, out);
}